// round 3
// baseline (speedup 1.0000x reference)
#include <cuda_runtime.h>
#include <cuda_bf16.h>

// Problem constants (fixed by setup_inputs): B=8, N=128, T=1024, K=3
#define BB   8
#define NN   128
#define TT   1024
#define VPAD 1152   // T + N - 1 = 1151, rounded up (zero-padded tail)
#define PTS  8      // points per thread
#define TPR  (TT / PTS)        // 128 threads per row
#define RPC  2                 // rows per CTA -> 256 threads

__device__ float g_stdv[BB * VPAD];

__global__ void prep_std_kernel(const float* __restrict__ k) {
    int idx = blockIdx.x * blockDim.x + threadIdx.x;
    if (idx >= BB * VPAD) return;
    int b = idx / VPAD;
    int t = idx - b * VPAD;
    float v = 0.0f;
    if (t < TT) {
        size_t off = ((size_t)(b * BB + b) * NN * TT + t) * 2;  // k_gp[b,b,0,t]
        v = k[off];
    }
    g_stdv[idx] = sqrtf(fmaxf(v, 0.0f));
}

struct Params {
    float one_m, coef, halfcoef, inv2pi;
    bool  fast;
};

// Compute (c0, d = c1 * k_ntk) for a single point t of a row.
__device__ __forceinline__ void point_cd(
    const float2* __restrict__ krow,
    const float* __restrict__ sx, const float* __restrict__ sy,
    int t, const Params& P, float& c0, float& d)
{
    const float RL  = 1.0f - 1e-6f;
    const float EPS = 1e-12f;
    const float PIf = 3.14159265358979323846f;
    const float2 kv = krow[t];
    const float sxy = sx[t] * sy[t];
    if (P.fast) {
        const float lim = RL * sxy;
        c0 = P.halfcoef * fminf(fmaxf(kv.x, -lim), lim);
        d  = P.halfcoef * kv.y;
    } else {
        const float denom = fmaxf(sxy, EPS);
        float rho = fminf(fmaxf(kv.x / denom, -RL), RL);
        const float theta = acosf(rho);
        const float s     = sqrtf(fmaxf(1.0f - rho * rho, 0.0f));
        const float tpart = P.coef * PIf - P.one_m * theta;
        c0 = sxy * P.inv2pi * (P.one_m * s + rho * tpart);
        d  = tpart * P.inv2pi * kv.y;
    }
}

__global__ __launch_bounds__(TPR * RPC) void fused_arc_conv_kernel(
    const float* __restrict__ k,
    const float* __restrict__ leak,
    const float* __restrict__ alpha,
    const float* __restrict__ beta,
    float* __restrict__ out)
{
    const int tid  = threadIdx.x;
    const int lt   = tid & (TPR - 1);            // thread within row
    const int rsub = tid >> 7;                   // 0 / 1
    const int row  = blockIdx.x * RPC + rsub;    // 0 .. B*B*N-1, layout (i,j,n)
    const int n    = row & (NN - 1);
    const int ij   = row >> 7;
    const int j    = ij & (BB - 1);
    const int i    = ij >> 3;

    const float a  = fmaxf(leak[0], 0.0f);
    const float w0 = fmaxf(alpha[0], 0.0f);
    const float w1 = fmaxf(alpha[1], 0.0f);
    const float w2 = fmaxf(alpha[2], 0.0f);
    const float bv = fmaxf(beta[0], 0.0f);

    const float PIf = 3.14159265358979323846f;
    Params P;
    P.one_m    = (1.0f - a) * (1.0f - a);
    P.coef     = 1.0f + a * a;
    P.halfcoef = 0.5f * P.coef;
    P.inv2pi   = 1.0f / (2.0f * PIf);
    P.fast     = (P.one_m == 0.0f);
    const float RL  = 1.0f - 1e-6f;
    const float EPS = 1e-12f;

    const int t8 = lt * PTS;

    const float2* __restrict__ krow = reinterpret_cast<const float2*>(k) + (size_t)row * TT;
    float4* __restrict__ orow4      = reinterpret_cast<float4*>(out)     + (size_t)row * (TT / 2);
    const float* __restrict__ sx = g_stdv + i * VPAD;       // std_x[t]
    const float* __restrict__ sy = g_stdv + j * VPAD + n;   // std_y[t] = stdv[j, n+t]

    // ---- batched loads: 4x LDG.128 (k), 2x LDG.128 (sx), 8 scalar (sy) ----
    const float4* kr4 = reinterpret_cast<const float4*>(krow + t8);
    const float4 ka = kr4[0], kb = kr4[1], kc = kr4[2], kd = kr4[3];
    const float4 sx0 = *reinterpret_cast<const float4*>(sx + t8);
    const float4 sx1 = *reinterpret_cast<const float4*>(sx + t8 + 4);

    float sya[PTS];
    #pragma unroll
    for (int q = 0; q < PTS; ++q) sya[q] = sy[t8 + q];

    const float kgp[PTS] = {ka.x, ka.z, kb.x, kb.z, kc.x, kc.z, kd.x, kd.z};
    const float knt[PTS] = {ka.y, ka.w, kb.y, kb.w, kc.y, kc.w, kd.y, kd.w};
    const float sxa[PTS] = {sx0.x, sx0.y, sx0.z, sx0.w, sx1.x, sx1.y, sx1.z, sx1.w};

    float c0[PTS], d[PTS];
    if (P.fast) {
        #pragma unroll
        for (int q = 0; q < PTS; ++q) {
            const float sxy = sxa[q] * sya[q];
            const float lim = RL * sxy;
            c0[q] = P.halfcoef * fminf(fmaxf(kgp[q], -lim), lim);
            d[q]  = P.halfcoef * knt[q];
        }
    } else {
        #pragma unroll 1
        for (int q = 0; q < PTS; ++q) {
            const float sxy   = sxa[q] * sya[q];
            const float denom = fmaxf(sxy, EPS);
            float rho = fminf(fmaxf(kgp[q] / denom, -RL), RL);
            const float theta = acosf(rho);
            const float s     = sqrtf(fmaxf(1.0f - rho * rho, 0.0f));
            const float tpart = P.coef * PIf - P.one_m * theta;
            c0[q] = sxy * P.inv2pi * (P.one_m * s + rho * tpart);
            d[q]  = tpart * P.inv2pi * knt[q];
        }
    }

    // ---- halos: shfl within warp, recompute at warp boundaries ----
    const unsigned lane = tid & 31u;
    float L0 = __shfl_up_sync(0xffffffffu, c0[PTS - 1], 1);
    float L1 = __shfl_up_sync(0xffffffffu, d[PTS - 1], 1);
    float R0 = __shfl_down_sync(0xffffffffu, c0[0], 1);
    float R1 = __shfl_down_sync(0xffffffffu, d[0], 1);
    if (lane == 0) {
        if (t8 == 0) { L0 = 0.0f; L1 = 0.0f; }
        else point_cd(krow, sx, sy, t8 - 1, P, L0, L1);
    }
    if (lane == 31) {
        if (t8 + PTS == TT) { R0 = 0.0f; R1 = 0.0f; }
        else point_cd(krow, sx, sy, t8 + PTS, P, R0, R1);
    }

    // ---- 3-tap conv entirely in registers ----
    float kg[PTS], kn[PTS];
    #pragma unroll
    for (int q = 0; q < PTS; ++q) {
        const float pc0 = (q == 0)       ? L0 : c0[q - 1];
        const float nc0 = (q == PTS - 1) ? R0 : c0[q + 1];
        const float pd  = (q == 0)       ? L1 : d[q - 1];
        const float nd  = (q == PTS - 1) ? R1 : d[q + 1];
        kg[q] = w0 * pc0 + w1 * c0[q] + w2 * nc0;
        kn[q] = w0 * pd  + w1 * d[q]  + w2 * nd + kg[q];
    }

    // ---- 4x STG.128 ----
    #pragma unroll
    for (int q = 0; q < 4; ++q) {
        orow4[lt * 4 + q] = make_float4(kg[2 * q] + bv, kn[2 * q] + bv,
                                        kg[2 * q + 1] + bv, kn[2 * q + 1] + bv);
    }
}

extern "C" void kernel_launch(void* const* d_in, const int* in_sizes, int n_in,
                              void* d_out, int out_size) {
    const float* k     = (const float*)d_in[0];
    const float* leak  = (const float*)d_in[1];
    const float* alpha = (const float*)d_in[2];
    const float* beta  = (const float*)d_in[3];
    float* out = (float*)d_out;

    prep_std_kernel<<<(BB * VPAD + 255) / 256, 256>>>(k);
    fused_arc_conv_kernel<<<BB * BB * NN / RPC, TPR * RPC>>>(k, leak, alpha, beta, out);
}

// round 4
// speedup vs baseline: 1.1748x; 1.1748x over previous
#include <cuda_runtime.h>
#include <cuda_bf16.h>

// Problem constants (fixed by setup_inputs): B=8, N=128, T=1024, K=3
#define BB    8
#define NN    128
#define TT    1024
#define VPAD  1152              // T + N - 1 = 1151, rounded up (zero-padded tail)
#define WPC   8                 // warps (rows) per CTA
#define STEPS (TT / 32)         // 32 steps of 32 points per warp

__device__ float g_stdv[BB * VPAD];

__global__ void prep_std_kernel(const float* __restrict__ k) {
    int idx = blockIdx.x * blockDim.x + threadIdx.x;
    if (idx >= BB * VPAD) return;
    int b = idx / VPAD;
    int t = idx - b * VPAD;
    float v = 0.0f;
    if (t < TT) {
        size_t off = ((size_t)(b * BB + b) * NN * TT + t) * 2;  // k_gp[b,b,0,t]
        v = k[off];
    }
    g_stdv[idx] = sqrtf(fmaxf(v, 0.0f));
}

struct Params {
    float one_m, coef, halfcoef, inv2pi;
    bool  fast;
};

// (c0, d = c1 * k_ntk) for point t of this row. All loads coalesced across the warp.
__device__ __forceinline__ float2 point_cd(
    const float2* __restrict__ krow,
    const float* __restrict__ sx, const float* __restrict__ sy,
    int t, const Params& P)
{
    const float RL  = 1.0f - 1e-6f;
    const float EPS = 1e-12f;
    const float PIf = 3.14159265358979323846f;
    const float2 kv = __ldg(krow + t);
    const float sxy = __ldg(sx + t) * __ldg(sy + t);
    float2 r;
    if (P.fast) {
        const float lim = RL * sxy;
        r.x = P.halfcoef * fminf(fmaxf(kv.x, -lim), lim);
        r.y = P.halfcoef * kv.y;
    } else {
        const float denom = fmaxf(sxy, EPS);
        float rho = fminf(fmaxf(kv.x / denom, -RL), RL);
        const float theta = acosf(rho);
        const float s     = sqrtf(fmaxf(1.0f - rho * rho, 0.0f));
        const float tpart = P.coef * PIf - P.one_m * theta;
        r.x = sxy * P.inv2pi * (P.one_m * s + rho * tpart);
        r.y = tpart * P.inv2pi * kv.y;
    }
    return r;
}

__global__ __launch_bounds__(32 * WPC) void fused_arc_conv_kernel(
    const float* __restrict__ k,
    const float* __restrict__ leak,
    const float* __restrict__ alpha,
    const float* __restrict__ beta,
    float* __restrict__ out)
{
    const int warp = threadIdx.x >> 5;
    const int lane = threadIdx.x & 31;
    const int row  = blockIdx.x * WPC + warp;    // 0 .. B*B*N-1, layout (i,j,n)
    const int n    = row & (NN - 1);
    const int ij   = row >> 7;
    const int j    = ij & (BB - 1);
    const int i    = ij >> 3;

    const float a  = fmaxf(leak[0], 0.0f);
    const float w0 = fmaxf(alpha[0], 0.0f);
    const float w1 = fmaxf(alpha[1], 0.0f);
    const float w2 = fmaxf(alpha[2], 0.0f);
    const float bv = fmaxf(beta[0], 0.0f);

    const float PIf = 3.14159265358979323846f;
    Params P;
    P.one_m    = (1.0f - a) * (1.0f - a);
    P.coef     = 1.0f + a * a;
    P.halfcoef = 0.5f * P.coef;
    P.inv2pi   = 1.0f / (2.0f * PIf);
    P.fast     = (P.one_m == 0.0f);

    const float2* __restrict__ krow = reinterpret_cast<const float2*>(k) + (size_t)row * TT;
    float2* __restrict__ orow       = reinterpret_cast<float2*>(out)     + (size_t)row * TT;
    const float* __restrict__ sx = g_stdv + i * VPAD;       // std_x[t]
    const float* __restrict__ sy = g_stdv + j * VPAD + n;   // std_y[t] = stdv[j, n+t]

    const unsigned FULL = 0xffffffffu;

    // software pipeline: cd_cur holds step s, compute step s+1 before convolving s
    float2 cd_cur = point_cd(krow, sx, sy, lane, P);
    float carryC = 0.0f, carryD = 0.0f;          // lane-31 value of previous step

    #pragma unroll 4
    for (int s = 0; s < STEPS; ++s) {
        float2 cd_next = make_float2(0.0f, 0.0f);
        if (s < STEPS - 1)
            cd_next = point_cd(krow, sx, sy, (s + 1) * 32 + lane, P);

        float LC = __shfl_up_sync(FULL, cd_cur.x, 1);
        float LD = __shfl_up_sync(FULL, cd_cur.y, 1);
        if (lane == 0) { LC = carryC; LD = carryD; }

        float RC = __shfl_down_sync(FULL, cd_cur.x, 1);
        float RD = __shfl_down_sync(FULL, cd_cur.y, 1);
        const float nC0 = __shfl_sync(FULL, cd_next.x, 0);
        const float nD0 = __shfl_sync(FULL, cd_next.y, 0);
        if (lane == 31) { RC = nC0; RD = nD0; }

        const float kg = w0 * LC + w1 * cd_cur.x + w2 * RC;
        const float kn = w0 * LD + w1 * cd_cur.y + w2 * RD + kg;
        orow[s * 32 + lane] = make_float2(kg + bv, kn + bv);

        carryC = __shfl_sync(FULL, cd_cur.x, 31);
        carryD = __shfl_sync(FULL, cd_cur.y, 31);
        cd_cur = cd_next;
    }
}

extern "C" void kernel_launch(void* const* d_in, const int* in_sizes, int n_in,
                              void* d_out, int out_size) {
    const float* k     = (const float*)d_in[0];
    const float* leak  = (const float*)d_in[1];
    const float* alpha = (const float*)d_in[2];
    const float* beta  = (const float*)d_in[3];
    float* out = (float*)d_out;

    prep_std_kernel<<<(BB * VPAD + 255) / 256, 256>>>(k);
    fused_arc_conv_kernel<<<BB * BB * NN / WPC, 32 * WPC>>>(k, leak, alpha, beta, out);
}

// round 5
// speedup vs baseline: 1.5231x; 1.2965x over previous
#include <cuda_runtime.h>
#include <cuda_bf16.h>

// Problem constants (fixed by setup_inputs): B=8, N=128, T=1024, K=3
#define BB   8
#define NN   128
#define TT   1024
#define ITERS (TT / 256)   // 4

__global__ __launch_bounds__(256) void fused_arc_conv_kernel(
    const float* __restrict__ k,
    const float* __restrict__ leak,
    const float* __restrict__ alpha,
    const float* __restrict__ beta,
    float* __restrict__ out)
{
    __shared__ float s0[TT + 2];
    __shared__ float s1[TT + 2];

    const int row = blockIdx.x;          // 0 .. B*B*N-1, layout (i,j,n)
    const int n   = row & (NN - 1);
    const int ij  = row >> 7;
    const int j   = ij & (BB - 1);
    const int i   = ij >> 3;

    const float a  = fmaxf(leak[0], 0.0f);
    const float w0 = fmaxf(alpha[0], 0.0f);
    const float w1 = fmaxf(alpha[1], 0.0f);
    const float w2 = fmaxf(alpha[2], 0.0f);
    const float bv = fmaxf(beta[0], 0.0f);

    const float PIf      = 3.14159265358979323846f;
    const float one_m    = (1.0f - a) * (1.0f - a);
    const float coef     = 1.0f + a * a;
    const float halfcoef = 0.5f * coef;
    const float inv2pi   = 1.0f / (2.0f * PIf);
    const float RL       = 1.0f - 1e-6f;
    const float EPS      = 1e-12f;
    const bool  fast     = (one_m == 0.0f);

    const float2* __restrict__ krow = reinterpret_cast<const float2*>(k) + (size_t)row * TT;
    float2* __restrict__ orow       = reinterpret_cast<float2*>(out)     + (size_t)row * TT;
    // diagonal rows holding the variance vectors (L2-resident: shared by 1024 CTAs each)
    const float2* __restrict__ kdi = reinterpret_cast<const float2*>(k) + (size_t)(i * BB + i) * NN * TT;
    const float2* __restrict__ kdj = reinterpret_cast<const float2*>(k) + (size_t)(j * BB + j) * NN * TT;

    const int tid = threadIdx.x;

    // ---------- phase 1: load + pointwise (all loads front-batched) ----------
    float2 kv[ITERS];
    float  vx[ITERS], vy[ITERS];
    #pragma unroll
    for (int it = 0; it < ITERS; ++it) {
        const int t = it * 256 + tid;
        kv[it] = __ldg(krow + t);
        vx[it] = __ldg(&kdi[t].x);                               // v[i, t]
        const int ty = n + t;
        vy[it] = (ty < TT) ? __ldg(&kdj[ty].x) : 0.0f;           // v_pad[j, n+t]
    }

    float c0r[ITERS], dr[ITERS];
    if (fast) {
        #pragma unroll
        for (int it = 0; it < ITERS; ++it) {
            const float sxy = sqrtf(fmaxf(vx[it], 0.0f)) * sqrtf(fmaxf(vy[it], 0.0f));
            const float lim = RL * sxy;
            c0r[it] = halfcoef * fminf(fmaxf(kv[it].x, -lim), lim);
            dr[it]  = halfcoef * kv[it].y;
        }
    } else {
        #pragma unroll 1
        for (int it = 0; it < ITERS; ++it) {
            const float sxy   = sqrtf(fmaxf(vx[it], 0.0f)) * sqrtf(fmaxf(vy[it], 0.0f));
            const float denom = fmaxf(sxy, EPS);
            float rho = fminf(fmaxf(kv[it].x / denom, -RL), RL);
            const float theta = acosf(rho);
            const float s     = sqrtf(fmaxf(1.0f - rho * rho, 0.0f));
            const float tpart = coef * PIf - one_m * theta;
            c0r[it] = sxy * inv2pi * (one_m * s + rho * tpart);
            dr[it]  = tpart * inv2pi * kv[it].y;
        }
    }

    #pragma unroll
    for (int it = 0; it < ITERS; ++it) {
        const int t = it * 256 + tid;
        s0[t + 1] = c0r[it];
        s1[t + 1] = dr[it];
    }
    if (tid == 0) {
        s0[0] = 0.0f; s1[0] = 0.0f;
        s0[TT + 1] = 0.0f; s1[TT + 1] = 0.0f;
    }
    __syncthreads();

    // ---------- phase 2: 3-tap conv (centers in regs, halos from smem) ----------
    #pragma unroll
    for (int it = 0; it < ITERS; ++it) {
        const int t = it * 256 + tid;
        const float kg = w0 * s0[t] + w1 * c0r[it] + w2 * s0[t + 2];
        const float kn = w0 * s1[t] + w1 * dr[it]  + w2 * s1[t + 2] + kg;
        orow[t] = make_float2(kg + bv, kn + bv);
    }
}

extern "C" void kernel_launch(void* const* d_in, const int* in_sizes, int n_in,
                              void* d_out, int out_size) {
    const float* k     = (const float*)d_in[0];
    const float* leak  = (const float*)d_in[1];
    const float* alpha = (const float*)d_in[2];
    const float* beta  = (const float*)d_in[3];
    float* out = (float*)d_out;

    fused_arc_conv_kernel<<<BB * BB * NN, 256>>>(k, leak, alpha, beta, out);
}